// round 10
// baseline (speedup 1.0000x reference)
#include <cuda_runtime.h>
#include <cuda_bf16.h>
#include <cuda_fp16.h>
#include <math.h>
#include <stdint.h>

#define NN   100000
#define NE   1600000
#define CIN  256
#define HID  128
#define COUT 16
#define NBLK 98          // ceil(NN/1024)

// ---------------- scratch (__device__ globals; no allocs allowed) ----------
__device__ __half          g_hs16[(size_t)(NN + 1) * HID]; // raw h, +1 zero row
__device__ int             g_deg[NN];
__device__ float           g_dinv[NN];
__device__ int             g_psc[NN];
__device__ int             g_off[NN + 1];
__device__ int             g_wptr[NN];
__device__ int             g_bsum[NBLK];
__device__ int             g_esrc[NE];
__device__ int             g_is64;
__device__ __nv_bfloat16   g_WT[HID * CIN];   // W^T bf16 [n][k]

__device__ __forceinline__ uint32_t smem_u32(const void* p) {
    uint32_t a;
    asm("{ .reg .u64 t; cvta.to.shared.u64 t, %1; cvt.u32.u64 %0, t; }"
        : "=r"(a) : "l"(p));
    return a;
}
__device__ __forceinline__ uint32_t swz128(uint32_t off) {
    return off ^ ((off >> 3) & 0x70);
}
__device__ __forceinline__ void ldsm_x4(uint32_t* r, uint32_t addr) {
    asm volatile("ldmatrix.sync.aligned.m8n8.x4.shared.b16 {%0,%1,%2,%3}, [%4];"
                 : "=r"(r[0]), "=r"(r[1]), "=r"(r[2]), "=r"(r[3]) : "r"(addr));
}
__device__ __forceinline__ void mma_bf16(float* d, const uint32_t* a,
                                         uint32_t b0, uint32_t b1) {
    asm volatile("mma.sync.aligned.m16n8k16.row.col.f32.bf16.bf16.f32 "
                 "{%0,%1,%2,%3}, {%4,%5,%6,%7}, {%8,%9}, {%0,%1,%2,%3};"
                 : "+f"(d[0]), "+f"(d[1]), "+f"(d[2]), "+f"(d[3])
                 : "r"(a[0]), "r"(a[1]), "r"(a[2]), "r"(a[3]), "r"(b0), "r"(b1));
}
__device__ __forceinline__ uint32_t cvt_bf16x2(float hi, float lo) {
    uint32_t r;
    asm("cvt.rn.bf16x2.f32 %0, %1, %2;" : "=r"(r) : "f"(hi), "f"(lo));
    return r;
}

// ---------------------------------------------------------------------------
// MAIN chain: W -> bf16 W^T, zero hs16 row NN
// ---------------------------------------------------------------------------
__global__ void k_init_w(const float* __restrict__ W) {
    int i = blockIdx.x * blockDim.x + threadIdx.x;
    if (i < CIN * HID) {
        int k = i >> 7, n = i & 127;
        g_WT[n * CIN + k] = __float2bfloat16_rn(W[i]);
    }
    if (i < 16)
        ((uint4*)(g_hs16 + (size_t)NN * HID))[i] = make_uint4(0u, 0u, 0u, 0u);
}

// SIDE chain: dtype sniff (1 warp)
__global__ void k_sniff(const int* __restrict__ e32) {
    if (threadIdx.x == 0) {
        int is64 = 1;
        #pragma unroll 1
        for (int j = 0; j < 64; j++)
            if (e32[2 * j + 1] != 0) { is64 = 0; break; }
        g_is64 = is64;
    }
}

__global__ void k_deg(const void* __restrict__ eptr) {
    const long long* e64 = (const long long*)eptr;
    const int*       e32 = (const int*)eptr;
    const int is64 = g_is64;
    for (int e = blockIdx.x * blockDim.x + threadIdx.x; e < NE;
         e += gridDim.x * blockDim.x) {
        int d = is64 ? (int)e64[NE + e] : e32[NE + e];
        atomicAdd(&g_deg[d], 1);
    }
}

__global__ __launch_bounds__(1024) void k_scanA() {
    __shared__ int ss[1024];
    const int t = threadIdx.x;
    const int i = blockIdx.x * 1024 + t;
    int v = (i < NN) ? g_deg[i] : 0;
    ss[t] = v;
    __syncthreads();
    #pragma unroll
    for (int off = 1; off < 1024; off <<= 1) {
        int add = (t >= off) ? ss[t - off] : 0;
        __syncthreads();
        ss[t] += add;
        __syncthreads();
    }
    if (i < NN) g_psc[i] = ss[t] - v;
    if (t == 1023) g_bsum[blockIdx.x] = ss[1023];
}

// scanC with inlined block-offset recompute (replaces scanB)
__global__ __launch_bounds__(256) void k_scanC() {
    __shared__ int s_boff;
    const int i = blockIdx.x * 256 + threadIdx.x;
    if (threadIdx.x == 0) {
        int blk = (blockIdx.x * 256) >> 10;   // owning scanA block
        int r0 = 0, r1 = 0, r2 = 0, r3 = 0;
        int b = 0;
        for (; b + 4 <= blk; b += 4) {
            r0 += g_bsum[b];     r1 += g_bsum[b + 1];
            r2 += g_bsum[b + 2]; r3 += g_bsum[b + 3];
        }
        for (; b < blk; b++) r0 += g_bsum[b];
        s_boff = r0 + r1 + r2 + r3;
    }
    __syncthreads();
    if (i < NN) {
        int o = g_psc[i] + s_boff;
        g_off[i]  = o;
        g_wptr[i] = o;
        g_dinv[i] = rsqrtf((float)(g_deg[i] + 1));
    }
    if (i == 0) g_off[NN] = NE;   // total degree == NE by construction
}

__global__ void k_sort(const void* __restrict__ eptr) {
    const long long* e64 = (const long long*)eptr;
    const int*       e32 = (const int*)eptr;
    const int is64 = g_is64;
    for (int e = blockIdx.x * blockDim.x + threadIdx.x; e < NE;
         e += gridDim.x * blockDim.x) {
        int s = is64 ? (int)e64[e]      : e32[e];
        int d = is64 ? (int)e64[NE + e] : e32[NE + e];
        int pos = atomicAdd(&g_wptr[d], 1);
        g_esrc[pos] = s;
    }
}

// ---------------------------------------------------------------------------
// GEMM: h = x @ W_conv, single-pass bf16 mma.sync, fp32 accum.
// ---------------------------------------------------------------------------
#define TILE_B   16384
#define OFF_A    0
#define OFF_B    16384
#define SMEM_DYN (2 * TILE_B + 256)

__global__ __launch_bounds__(256, 2) void k_gemm_tc(const float* __restrict__ x) {
    extern __shared__ char dsm_raw[];
    char* const base = (char*)(((uintptr_t)dsm_raw + 127) & ~(uintptr_t)127);
    const uint32_t base_u = smem_u32(base);

    const int tid  = threadIdx.x;
    const int lane = tid & 31;
    const int wid  = tid >> 5;
    const int wm   = wid & 3;
    const int wn   = wid >> 2;
    const int row0 = blockIdx.x * 128;

    float acc[2][8][4];
    #pragma unroll
    for (int i = 0; i < 2; i++)
        #pragma unroll
        for (int j = 0; j < 8; j++)
            #pragma unroll
            for (int q = 0; q < 4; q++) acc[i][j][q] = 0.f;

    const float4* x4 = (const float4*)x;

    float4 v[8];
    #pragma unroll
    for (int i = 0; i < 8; i++) {
        int idx = i * 256 + tid;
        int r = idx >> 4, q = idx & 15;
        int node = row0 + r;
        v[i] = (node < NN) ? x4[(size_t)node * (CIN / 4) + q]
                           : make_float4(0.f, 0.f, 0.f, 0.f);
    }

    for (int c = 0; c < 4; c++) {
        #pragma unroll
        for (int i = 0; i < 8; i++) {
            int idx = i * 256 + tid;
            int r = idx >> 4, q = idx & 15;
            float4 w = v[i];
            uint32_t h01 = cvt_bf16x2(w.y, w.x);
            uint32_t h23 = cvt_bf16x2(w.w, w.z);
            uint32_t so = swz128((uint32_t)(r * 128 + q * 8));
            *(uint2*)(base + OFF_A + so) = make_uint2(h01, h23);
        }
        #pragma unroll
        for (int i = 0; i < 4; i++) {
            int idx = i * 256 + tid;
            int n = idx >> 3, u = idx & 7;
            uint32_t so = swz128((uint32_t)(n * 128 + u * 16));
            const char* src = (const char*)g_WT + n * (CIN * 2) + c * 128 + u * 16;
            *(uint4*)(base + OFF_B + so) = *(const uint4*)src;
        }
        __syncthreads();

        if (c < 3) {
            #pragma unroll
            for (int i = 0; i < 8; i++) {
                int idx = i * 256 + tid;
                int r = idx >> 4, q = idx & 15;
                int node = row0 + r;
                v[i] = (node < NN)
                     ? x4[(size_t)node * (CIN / 4) + (c + 1) * 16 + q]
                     : make_float4(0.f, 0.f, 0.f, 0.f);
            }
        }

        #pragma unroll
        for (int ks = 0; ks < 4; ks++) {
            uint32_t ah[2][4];
            #pragma unroll
            for (int mi = 0; mi < 2; mi++) {
                uint32_t r = (uint32_t)(wm * 32 + mi * 16 + (lane & 15));
                uint32_t kb = (uint32_t)(ks * 32 + (lane >> 4) * 16);
                ldsm_x4(ah[mi], base_u + OFF_A + swz128(r * 128 + kb));
            }
            #pragma unroll
            for (int nj2 = 0; nj2 < 4; nj2++) {
                uint32_t n = (uint32_t)(wn * 64 + nj2 * 16 + (lane & 7)
                                        + ((lane >> 4) << 3));
                uint32_t kb = (uint32_t)(ks * 32 + ((lane >> 3) & 1) * 16);
                uint32_t bh[4];
                ldsm_x4(bh, base_u + OFF_B + swz128(n * 128 + kb));
                #pragma unroll
                for (int mi = 0; mi < 2; mi++) {
                    mma_bf16(acc[mi][nj2 * 2 + 0], ah[mi], bh[0], bh[1]);
                    mma_bf16(acc[mi][nj2 * 2 + 1], ah[mi], bh[2], bh[3]);
                }
            }
        }
        __syncthreads();
    }

    const int group = lane >> 2;
    const int qp    = lane & 3;
    #pragma unroll
    for (int mi = 0; mi < 2; mi++) {
        #pragma unroll
        for (int half = 0; half < 2; half++) {
            int r = wm * 32 + mi * 16 + half * 8 + group;
            int node = row0 + r;
            if (node < NN) {
                __half* hrow = g_hs16 + (size_t)node * HID;
                #pragma unroll
                for (int nj = 0; nj < 8; nj++) {
                    int col = wn * 64 + nj * 8 + qp * 2;
                    __half2 hh = __floats2half2_rn(
                        acc[mi][nj][half * 2 + 0],
                        acc[mi][nj][half * 2 + 1]);
                    *(__half2*)(hrow + col) = hh;
                }
            }
        }
    }
}

// ---------------------------------------------------------------------------
// Aggregate + final linear + log_softmax.  One warp per dst.
// ---------------------------------------------------------------------------
__global__ __launch_bounds__(256) void k_agg_final(const float* __restrict__ bc,
                                                   const float* __restrict__ Wl,
                                                   const float* __restrict__ bl,
                                                   float* __restrict__ out) {
    __shared__ float sW[HID][COUT + 1];
    __shared__ float sBc[HID];
    __shared__ float sBl[COUT];
    __shared__ float sStage[8][HID];
    for (int i = threadIdx.x; i < HID * COUT; i += 256) {
        int d = i >> 4, c = i & 15;
        sW[d][c] = Wl[i];
    }
    for (int i = threadIdx.x; i < HID; i += 256) sBc[i] = bc[i];
    if (threadIdx.x < COUT) sBl[threadIdx.x] = bl[threadIdx.x];
    __syncthreads();

    const int lane = threadIdx.x & 31;
    const int wblk = threadIdx.x >> 5;
    const int dst  = (blockIdx.x * blockDim.x + threadIdx.x) >> 5;
    if (dst >= NN) return;

    const int s0 = g_off[dst];
    const int s1 = g_off[dst + 1];
    const float di = g_dinv[dst];
    const uint4* hp = (const uint4*)g_hs16;
    const int seg = lane & 15;
    const int hlf = lane >> 4;

    float a0, a1, a2, a3, a4, a5, a6, a7;
    {
        int ssrc = hlf ? NN : dst;
        float cf = hlf ? 0.f : di;
        uint4 u = __ldg(hp + (size_t)ssrc * 16 + seg);
        float2 f0 = __half22float2(*(__half2*)&u.x);
        float2 f1 = __half22float2(*(__half2*)&u.y);
        float2 f2 = __half22float2(*(__half2*)&u.z);
        float2 f3 = __half22float2(*(__half2*)&u.w);
        a0 = f0.x * cf; a1 = f0.y * cf; a2 = f1.x * cf; a3 = f1.y * cf;
        a4 = f2.x * cf; a5 = f2.y * cf; a6 = f3.x * cf; a7 = f3.y * cf;
    }

    for (int b = s0; b < s1; b += 32) {
        int m = s1 - b; if (m > 32) m = 32;
        int   s  = (lane < m) ? __ldg(g_esrc + b + lane) : NN;
        float ds = (lane < m) ? __ldg(g_dinv + s) : 0.f;
        #pragma unroll 1
        for (int j = 0; j < m; j += 8) {
            int   e0 = __shfl_sync(0xffffffffu, s,  j + 0 + hlf);
            int   e1 = __shfl_sync(0xffffffffu, s,  j + 2 + hlf);
            int   e2 = __shfl_sync(0xffffffffu, s,  j + 4 + hlf);
            int   e3 = __shfl_sync(0xffffffffu, s,  j + 6 + hlf);
            float c0 = __shfl_sync(0xffffffffu, ds, j + 0 + hlf);
            float c1 = __shfl_sync(0xffffffffu, ds, j + 2 + hlf);
            float c2 = __shfl_sync(0xffffffffu, ds, j + 4 + hlf);
            float c3 = __shfl_sync(0xffffffffu, ds, j + 6 + hlf);
            uint4 u0 = __ldg(hp + (size_t)e0 * 16 + seg);
            uint4 u1 = __ldg(hp + (size_t)e1 * 16 + seg);
            uint4 u2 = __ldg(hp + (size_t)e2 * 16 + seg);
            uint4 u3 = __ldg(hp + (size_t)e3 * 16 + seg);
            {
                float2 f0 = __half22float2(*(__half2*)&u0.x);
                float2 f1 = __half22float2(*(__half2*)&u0.y);
                float2 f2 = __half22float2(*(__half2*)&u0.z);
                float2 f3 = __half22float2(*(__half2*)&u0.w);
                a0 = fmaf(f0.x, c0, a0); a1 = fmaf(f0.y, c0, a1);
                a2 = fmaf(f1.x, c0, a2); a3 = fmaf(f1.y, c0, a3);
                a4 = fmaf(f2.x, c0, a4); a5 = fmaf(f2.y, c0, a5);
                a6 = fmaf(f3.x, c0, a6); a7 = fmaf(f3.y, c0, a7);
            }
            {
                float2 f0 = __half22float2(*(__half2*)&u1.x);
                float2 f1 = __half22float2(*(__half2*)&u1.y);
                float2 f2 = __half22float2(*(__half2*)&u1.z);
                float2 f3 = __half22float2(*(__half2*)&u1.w);
                a0 = fmaf(f0.x, c1, a0); a1 = fmaf(f0.y, c1, a1);
                a2 = fmaf(f1.x, c1, a2); a3 = fmaf(f1.y, c1, a3);
                a4 = fmaf(f2.x, c1, a4); a5 = fmaf(f2.y, c1, a5);
                a6 = fmaf(f3.x, c1, a6); a7 = fmaf(f3.y, c1, a7);
            }
            {
                float2 f0 = __half22float2(*(__half2*)&u2.x);
                float2 f1 = __half22float2(*(__half2*)&u2.y);
                float2 f2 = __half22float2(*(__half2*)&u2.z);
                float2 f3 = __half22float2(*(__half2*)&u2.w);
                a0 = fmaf(f0.x, c2, a0); a1 = fmaf(f0.y, c2, a1);
                a2 = fmaf(f1.x, c2, a2); a3 = fmaf(f1.y, c2, a3);
                a4 = fmaf(f2.x, c2, a4); a5 = fmaf(f2.y, c2, a5);
                a6 = fmaf(f3.x, c2, a6); a7 = fmaf(f3.y, c2, a7);
            }
            {
                float2 f0 = __half22float2(*(__half2*)&u3.x);
                float2 f1 = __half22float2(*(__half2*)&u3.y);
                float2 f2 = __half22float2(*(__half2*)&u3.z);
                float2 f3 = __half22float2(*(__half2*)&u3.w);
                a0 = fmaf(f0.x, c3, a0); a1 = fmaf(f0.y, c3, a1);
                a2 = fmaf(f1.x, c3, a2); a3 = fmaf(f1.y, c3, a3);
                a4 = fmaf(f2.x, c3, a4); a5 = fmaf(f2.y, c3, a5);
                a6 = fmaf(f3.x, c3, a6); a7 = fmaf(f3.y, c3, a7);
            }
        }
    }

    a0 += __shfl_xor_sync(0xffffffffu, a0, 16);
    a1 += __shfl_xor_sync(0xffffffffu, a1, 16);
    a2 += __shfl_xor_sync(0xffffffffu, a2, 16);
    a3 += __shfl_xor_sync(0xffffffffu, a3, 16);
    a4 += __shfl_xor_sync(0xffffffffu, a4, 16);
    a5 += __shfl_xor_sync(0xffffffffu, a5, 16);
    a6 += __shfl_xor_sync(0xffffffffu, a6, 16);
    a7 += __shfl_xor_sync(0xffffffffu, a7, 16);

    if (hlf == 0) {
        float* st = &sStage[wblk][seg * 8];
        st[0] = a0; st[1] = a1; st[2] = a2; st[3] = a3;
        st[4] = a4; st[5] = a5; st[6] = a6; st[7] = a7;
    }
    __syncwarp();

    float na[4];
    #pragma unroll
    for (int t = 0; t < 4; t++) {
        float v = sStage[wblk][lane + 32 * t];
        na[t] = fmaxf(v * di + sBc[lane + 32 * t], 0.f);
    }

    float p[COUT];
    #pragma unroll
    for (int c = 0; c < COUT; c++) {
        p[c] = na[0] * sW[lane][c] + na[1] * sW[lane + 32][c]
             + na[2] * sW[lane + 64][c] + na[3] * sW[lane + 96][c];
    }
    #pragma unroll
    for (int off = 16; off > 0; off >>= 1)
        #pragma unroll
        for (int c = 0; c < COUT; c++)
            p[c] += __shfl_xor_sync(0xffffffffu, p[c], off);

    #pragma unroll
    for (int c = 0; c < COUT; c++) p[c] += sBl[c];

    float mx = p[0];
    #pragma unroll
    for (int c = 1; c < COUT; c++) mx = fmaxf(mx, p[c]);
    float sum = 0.f;
    #pragma unroll
    for (int c = 0; c < COUT; c++) sum += expf(p[c] - mx);
    float lse = mx + logf(sum);

    if (lane < COUT) out[(size_t)dst * COUT + lane] = p[lane] - lse;
}

// ---------------------------------------------------------------------------
extern "C" void kernel_launch(void* const* d_in, const int* in_sizes, int n_in,
                              void* d_out, int out_size) {
    const float* x      = (const float*)d_in[0];
    const void*  eidx   = d_in[1];
    const float* W_conv = (const float*)d_in[2];
    const float* b_conv = (const float*)d_in[3];
    const float* W_lin  = (const float*)d_in[4];
    const float* b_lin  = (const float*)d_in[5];
    float* out = (float*)d_out;

    // one-time handle creation (idempotent; identical node set every call)
    static cudaStream_t s_side = nullptr;
    static cudaEvent_t  ev_fork = nullptr, ev_join = nullptr;
    static void* p_deg = nullptr;
    if (s_side == nullptr) {
        cudaStreamCreateWithFlags(&s_side, cudaStreamNonBlocking);
        cudaEventCreateWithFlags(&ev_fork, cudaEventDisableTiming);
        cudaEventCreateWithFlags(&ev_join, cudaEventDisableTiming);
        cudaGetSymbolAddress(&p_deg, g_deg);
        cudaFuncSetAttribute(k_gemm_tc,
                             cudaFuncAttributeMaxDynamicSharedMemorySize,
                             SMEM_DYN);
    }

    // fork at t=0: side chain is fully independent of the W-split/GEMM chain
    cudaEventRecord(ev_fork, 0);
    cudaStreamWaitEvent(s_side, ev_fork, 0);

    // SIDE: zero degrees (memset node) -> sniff -> deg -> scan -> sort
    cudaMemsetAsync(p_deg, 0, NN * sizeof(int), s_side);
    k_sniff<<<1, 32, 0, s_side>>>((const int*)eidx);
    k_deg<<<1024, 256, 0, s_side>>>(eidx);
    k_scanA<<<NBLK, 1024, 0, s_side>>>();
    k_scanC<<<(NN + 255) / 256, 256, 0, s_side>>>();
    k_sort<<<1024, 256, 0, s_side>>>(eidx);
    cudaEventRecord(ev_join, s_side);

    // MAIN: W split then GEMM (no dependency on side chain)
    k_init_w<<<(CIN * HID + 255) / 256, 256>>>(W_conv);
    k_gemm_tc<<<(NN + 127) / 128, 256, SMEM_DYN>>>(x);

    // join, then aggregate + final
    cudaStreamWaitEvent(0, ev_join, 0);
    k_agg_final<<<(NN * 32 + 255) / 256, 256>>>(b_conv, W_lin, b_lin, out);
}

// round 11
// speedup vs baseline: 1.0502x; 1.0502x over previous
#include <cuda_runtime.h>
#include <cuda_bf16.h>
#include <cuda_fp16.h>
#include <math.h>
#include <stdint.h>

#define NN   100000
#define NE   1600000
#define CIN  256
#define HID  128
#define COUT 16
#define NBLK 98          // ceil(NN/1024)

// ---------------- scratch (__device__ globals; no allocs allowed) ----------
__device__ __half          g_hs16[(size_t)(NN + 1) * HID]; // raw h, +1 zero row
__device__ int             g_deg[NN];
__device__ float           g_dinv[NN];
__device__ int             g_psc[NN];
__device__ int             g_off[NN + 1];
__device__ int             g_wptr[NN];
__device__ int             g_bsum[NBLK];
__device__ int             g_esrc[NE];
__device__ int             g_is64;
__device__ __nv_bfloat16   g_WT[HID * CIN];   // W^T bf16 [n][k]

__device__ __forceinline__ uint32_t smem_u32(const void* p) {
    uint32_t a;
    asm("{ .reg .u64 t; cvta.to.shared.u64 t, %1; cvt.u32.u64 %0, t; }"
        : "=r"(a) : "l"(p));
    return a;
}
__device__ __forceinline__ uint32_t swz128(uint32_t off) {
    return off ^ ((off >> 3) & 0x70);
}
__device__ __forceinline__ void ldsm_x4(uint32_t* r, uint32_t addr) {
    asm volatile("ldmatrix.sync.aligned.m8n8.x4.shared.b16 {%0,%1,%2,%3}, [%4];"
                 : "=r"(r[0]), "=r"(r[1]), "=r"(r[2]), "=r"(r[3]) : "r"(addr));
}
__device__ __forceinline__ void mma_bf16(float* d, const uint32_t* a,
                                         uint32_t b0, uint32_t b1) {
    asm volatile("mma.sync.aligned.m16n8k16.row.col.f32.bf16.bf16.f32 "
                 "{%0,%1,%2,%3}, {%4,%5,%6,%7}, {%8,%9}, {%0,%1,%2,%3};"
                 : "+f"(d[0]), "+f"(d[1]), "+f"(d[2]), "+f"(d[3])
                 : "r"(a[0]), "r"(a[1]), "r"(a[2]), "r"(a[3]), "r"(b0), "r"(b1));
}
__device__ __forceinline__ uint32_t cvt_bf16x2(float hi, float lo) {
    uint32_t r;
    asm("cvt.rn.bf16x2.f32 %0, %1, %2;" : "=r"(r) : "f"(hi), "f"(lo));
    return r;
}

// ---------------------------------------------------------------------------
// MAIN chain: W -> bf16 W^T, zero hs16 row NN
// ---------------------------------------------------------------------------
__global__ void k_init_w(const float* __restrict__ W) {
    int i = blockIdx.x * blockDim.x + threadIdx.x;
    if (i < CIN * HID) {
        int k = i >> 7, n = i & 127;
        g_WT[n * CIN + k] = __float2bfloat16_rn(W[i]);
    }
    if (i < 16)
        ((uint4*)(g_hs16 + (size_t)NN * HID))[i] = make_uint4(0u, 0u, 0u, 0u);
}

// SIDE chain: dtype sniff (1 warp)
__global__ void k_sniff(const int* __restrict__ e32) {
    if (threadIdx.x == 0) {
        int is64 = 1;
        #pragma unroll 1
        for (int j = 0; j < 64; j++)
            if (e32[2 * j + 1] != 0) { is64 = 0; break; }
        g_is64 = is64;
    }
}

__global__ void k_deg(const void* __restrict__ eptr) {
    const long long* e64 = (const long long*)eptr;
    const int*       e32 = (const int*)eptr;
    const int is64 = g_is64;
    for (int e = blockIdx.x * blockDim.x + threadIdx.x; e < NE;
         e += gridDim.x * blockDim.x) {
        int d = is64 ? (int)e64[NE + e] : e32[NE + e];
        atomicAdd(&g_deg[d], 1);
    }
}

__global__ __launch_bounds__(1024) void k_scanA() {
    __shared__ int ss[1024];
    const int t = threadIdx.x;
    const int i = blockIdx.x * 1024 + t;
    int v = (i < NN) ? g_deg[i] : 0;
    ss[t] = v;
    __syncthreads();
    #pragma unroll
    for (int off = 1; off < 1024; off <<= 1) {
        int add = (t >= off) ? ss[t - off] : 0;
        __syncthreads();
        ss[t] += add;
        __syncthreads();
    }
    if (i < NN) g_psc[i] = ss[t] - v;
    if (t == 1023) g_bsum[blockIdx.x] = ss[1023];
}

// scanC with inlined block-offset recompute
__global__ __launch_bounds__(256) void k_scanC() {
    __shared__ int s_boff;
    const int i = blockIdx.x * 256 + threadIdx.x;
    if (threadIdx.x == 0) {
        int blk = (blockIdx.x * 256) >> 10;
        int r0 = 0, r1 = 0, r2 = 0, r3 = 0;
        int b = 0;
        for (; b + 4 <= blk; b += 4) {
            r0 += g_bsum[b];     r1 += g_bsum[b + 1];
            r2 += g_bsum[b + 2]; r3 += g_bsum[b + 3];
        }
        for (; b < blk; b++) r0 += g_bsum[b];
        s_boff = r0 + r1 + r2 + r3;
    }
    __syncthreads();
    if (i < NN) {
        int o = g_psc[i] + s_boff;
        g_off[i]  = o;
        g_wptr[i] = o;
        g_dinv[i] = rsqrtf((float)(g_deg[i] + 1));
    }
    if (i == 0) g_off[NN] = NE;
}

__global__ void k_sort(const void* __restrict__ eptr) {
    const long long* e64 = (const long long*)eptr;
    const int*       e32 = (const int*)eptr;
    const int is64 = g_is64;
    for (int e = blockIdx.x * blockDim.x + threadIdx.x; e < NE;
         e += gridDim.x * blockDim.x) {
        int s = is64 ? (int)e64[e]      : e32[e];
        int d = is64 ? (int)e64[NE + e] : e32[NE + e];
        int pos = atomicAdd(&g_wptr[d], 1);
        g_esrc[pos] = s;
    }
}

// ---------------------------------------------------------------------------
// GEMM: h = x @ W_conv, single-pass bf16 mma.sync, fp32 accum.
// ---------------------------------------------------------------------------
#define TILE_B   16384
#define OFF_A    0
#define OFF_B    16384
#define SMEM_DYN (2 * TILE_B + 256)

__global__ __launch_bounds__(256, 2) void k_gemm_tc(const float* __restrict__ x) {
    extern __shared__ char dsm_raw[];
    char* const base = (char*)(((uintptr_t)dsm_raw + 127) & ~(uintptr_t)127);
    const uint32_t base_u = smem_u32(base);

    const int tid  = threadIdx.x;
    const int lane = tid & 31;
    const int wid  = tid >> 5;
    const int wm   = wid & 3;
    const int wn   = wid >> 2;
    const int row0 = blockIdx.x * 128;

    float acc[2][8][4];
    #pragma unroll
    for (int i = 0; i < 2; i++)
        #pragma unroll
        for (int j = 0; j < 8; j++)
            #pragma unroll
            for (int q = 0; q < 4; q++) acc[i][j][q] = 0.f;

    const float4* x4 = (const float4*)x;

    float4 v[8];
    #pragma unroll
    for (int i = 0; i < 8; i++) {
        int idx = i * 256 + tid;
        int r = idx >> 4, q = idx & 15;
        int node = row0 + r;
        v[i] = (node < NN) ? x4[(size_t)node * (CIN / 4) + q]
                           : make_float4(0.f, 0.f, 0.f, 0.f);
    }

    for (int c = 0; c < 4; c++) {
        #pragma unroll
        for (int i = 0; i < 8; i++) {
            int idx = i * 256 + tid;
            int r = idx >> 4, q = idx & 15;
            float4 w = v[i];
            uint32_t h01 = cvt_bf16x2(w.y, w.x);
            uint32_t h23 = cvt_bf16x2(w.w, w.z);
            uint32_t so = swz128((uint32_t)(r * 128 + q * 8));
            *(uint2*)(base + OFF_A + so) = make_uint2(h01, h23);
        }
        #pragma unroll
        for (int i = 0; i < 4; i++) {
            int idx = i * 256 + tid;
            int n = idx >> 3, u = idx & 7;
            uint32_t so = swz128((uint32_t)(n * 128 + u * 16));
            const char* src = (const char*)g_WT + n * (CIN * 2) + c * 128 + u * 16;
            *(uint4*)(base + OFF_B + so) = *(const uint4*)src;
        }
        __syncthreads();

        if (c < 3) {
            #pragma unroll
            for (int i = 0; i < 8; i++) {
                int idx = i * 256 + tid;
                int r = idx >> 4, q = idx & 15;
                int node = row0 + r;
                v[i] = (node < NN)
                     ? x4[(size_t)node * (CIN / 4) + (c + 1) * 16 + q]
                     : make_float4(0.f, 0.f, 0.f, 0.f);
            }
        }

        #pragma unroll
        for (int ks = 0; ks < 4; ks++) {
            uint32_t ah[2][4];
            #pragma unroll
            for (int mi = 0; mi < 2; mi++) {
                uint32_t r = (uint32_t)(wm * 32 + mi * 16 + (lane & 15));
                uint32_t kb = (uint32_t)(ks * 32 + (lane >> 4) * 16);
                ldsm_x4(ah[mi], base_u + OFF_A + swz128(r * 128 + kb));
            }
            #pragma unroll
            for (int nj2 = 0; nj2 < 4; nj2++) {
                uint32_t n = (uint32_t)(wn * 64 + nj2 * 16 + (lane & 7)
                                        + ((lane >> 4) << 3));
                uint32_t kb = (uint32_t)(ks * 32 + ((lane >> 3) & 1) * 16);
                uint32_t bh[4];
                ldsm_x4(bh, base_u + OFF_B + swz128(n * 128 + kb));
                #pragma unroll
                for (int mi = 0; mi < 2; mi++) {
                    mma_bf16(acc[mi][nj2 * 2 + 0], ah[mi], bh[0], bh[1]);
                    mma_bf16(acc[mi][nj2 * 2 + 1], ah[mi], bh[2], bh[3]);
                }
            }
        }
        __syncthreads();
    }

    const int group = lane >> 2;
    const int qp    = lane & 3;
    #pragma unroll
    for (int mi = 0; mi < 2; mi++) {
        #pragma unroll
        for (int half = 0; half < 2; half++) {
            int r = wm * 32 + mi * 16 + half * 8 + group;
            int node = row0 + r;
            if (node < NN) {
                __half* hrow = g_hs16 + (size_t)node * HID;
                #pragma unroll
                for (int nj = 0; nj < 8; nj++) {
                    int col = wn * 64 + nj * 8 + qp * 2;
                    __half2 hh = __floats2half2_rn(
                        acc[mi][nj][half * 2 + 0],
                        acc[mi][nj][half * 2 + 1]);
                    *(__half2*)(hrow + col) = hh;
                }
            }
        }
    }
}

// ---------------------------------------------------------------------------
// Aggregate + final linear + log_softmax.  One warp per dst.
// Gather: HFMA2 half2 accumulation (flush to fp32 every <=16 edges).
// Epilogue: smem partial-stage + 16-lane column reduce + lane-parallel softmax.
// ---------------------------------------------------------------------------
__global__ __launch_bounds__(256) void k_agg_final(const float* __restrict__ bc,
                                                   const float* __restrict__ Wl,
                                                   const float* __restrict__ bl,
                                                   float* __restrict__ out) {
    __shared__ float sW[HID][COUT + 1];
    __shared__ float sBc[HID];
    __shared__ float sBl[COUT];
    __shared__ float sStage[8][HID];
    __shared__ float sP[8][32][COUT + 1];
    for (int i = threadIdx.x; i < HID * COUT; i += 256) {
        int d = i >> 4, c = i & 15;
        sW[d][c] = Wl[i];
    }
    for (int i = threadIdx.x; i < HID; i += 256) sBc[i] = bc[i];
    if (threadIdx.x < COUT) sBl[threadIdx.x] = bl[threadIdx.x];
    __syncthreads();

    const int lane = threadIdx.x & 31;
    const int wblk = threadIdx.x >> 5;
    const int dst  = (blockIdx.x * blockDim.x + threadIdx.x) >> 5;
    if (dst >= NN) return;

    const int s0 = g_off[dst];
    const int s1 = g_off[dst + 1];
    const float di = g_dinv[dst];
    const uint4* hp = (const uint4*)g_hs16;
    const int seg = lane & 15;
    const int hlf = lane >> 4;

    float a0, a1, a2, a3, a4, a5, a6, a7;
    {   // self row: half 0 dst row with coeff di (fp32), half 1 zero row
        int ssrc = hlf ? NN : dst;
        float cf = hlf ? 0.f : di;
        uint4 u = __ldg(hp + (size_t)ssrc * 16 + seg);
        float2 f0 = __half22float2(*(__half2*)&u.x);
        float2 f1 = __half22float2(*(__half2*)&u.y);
        float2 f2 = __half22float2(*(__half2*)&u.z);
        float2 f3 = __half22float2(*(__half2*)&u.w);
        a0 = f0.x * cf; a1 = f0.y * cf; a2 = f1.x * cf; a3 = f1.y * cf;
        a4 = f2.x * cf; a5 = f2.y * cf; a6 = f3.x * cf; a7 = f3.y * cf;
    }

    const __half2 hz = __floats2half2_rn(0.f, 0.f);

    for (int b = s0; b < s1; b += 32) {
        int m = s1 - b; if (m > 32) m = 32;
        int   s   = (lane < m) ? __ldg(g_esrc + b + lane) : NN;
        float dsf = (lane < m) ? __ldg(g_dinv + s) : 0.f;
        __half2 dh2 = __float2half2_rn(dsf);
        uint32_t dcode = *(uint32_t*)&dh2;

        __half2 hc0 = hz, hc1 = hz, hc2 = hz, hc3 = hz;
        #pragma unroll 1
        for (int j = 0; j < m; j += 8) {
            int      e0 = __shfl_sync(0xffffffffu, s,     j + 0 + hlf);
            int      e1 = __shfl_sync(0xffffffffu, s,     j + 2 + hlf);
            int      e2 = __shfl_sync(0xffffffffu, s,     j + 4 + hlf);
            int      e3 = __shfl_sync(0xffffffffu, s,     j + 6 + hlf);
            uint32_t q0 = __shfl_sync(0xffffffffu, dcode, j + 0 + hlf);
            uint32_t q1 = __shfl_sync(0xffffffffu, dcode, j + 2 + hlf);
            uint32_t q2 = __shfl_sync(0xffffffffu, dcode, j + 4 + hlf);
            uint32_t q3 = __shfl_sync(0xffffffffu, dcode, j + 6 + hlf);
            uint4 u0 = __ldg(hp + (size_t)e0 * 16 + seg);
            uint4 u1 = __ldg(hp + (size_t)e1 * 16 + seg);
            uint4 u2 = __ldg(hp + (size_t)e2 * 16 + seg);
            uint4 u3 = __ldg(hp + (size_t)e3 * 16 + seg);
            __half2 c0 = *(__half2*)&q0, c1 = *(__half2*)&q1;
            __half2 c2 = *(__half2*)&q2, c3 = *(__half2*)&q3;
            hc0 = __hfma2(*(__half2*)&u0.x, c0, hc0);
            hc1 = __hfma2(*(__half2*)&u0.y, c0, hc1);
            hc2 = __hfma2(*(__half2*)&u0.z, c0, hc2);
            hc3 = __hfma2(*(__half2*)&u0.w, c0, hc3);
            hc0 = __hfma2(*(__half2*)&u1.x, c1, hc0);
            hc1 = __hfma2(*(__half2*)&u1.y, c1, hc1);
            hc2 = __hfma2(*(__half2*)&u1.z, c1, hc2);
            hc3 = __hfma2(*(__half2*)&u1.w, c1, hc3);
            hc0 = __hfma2(*(__half2*)&u2.x, c2, hc0);
            hc1 = __hfma2(*(__half2*)&u2.y, c2, hc1);
            hc2 = __hfma2(*(__half2*)&u2.z, c2, hc2);
            hc3 = __hfma2(*(__half2*)&u2.w, c2, hc3);
            hc0 = __hfma2(*(__half2*)&u3.x, c3, hc0);
            hc1 = __hfma2(*(__half2*)&u3.y, c3, hc1);
            hc2 = __hfma2(*(__half2*)&u3.z, c3, hc2);
            hc3 = __hfma2(*(__half2*)&u3.w, c3, hc3);
            if (j == 8) {   // flush after 16 edges to bound half-accum error
                float2 f0 = __half22float2(hc0);
                float2 f1 = __half22float2(hc1);
                float2 f2 = __half22float2(hc2);
                float2 f3 = __half22float2(hc3);
                a0 += f0.x; a1 += f0.y; a2 += f1.x; a3 += f1.y;
                a4 += f2.x; a5 += f2.y; a6 += f3.x; a7 += f3.y;
                hc0 = hz; hc1 = hz; hc2 = hz; hc3 = hz;
            }
        }
        {   // final flush for this batch
            float2 f0 = __half22float2(hc0);
            float2 f1 = __half22float2(hc1);
            float2 f2 = __half22float2(hc2);
            float2 f3 = __half22float2(hc3);
            a0 += f0.x; a1 += f0.y; a2 += f1.x; a3 += f1.y;
            a4 += f2.x; a5 += f2.y; a6 += f3.x; a7 += f3.y;
        }
    }

    // combine halves
    a0 += __shfl_xor_sync(0xffffffffu, a0, 16);
    a1 += __shfl_xor_sync(0xffffffffu, a1, 16);
    a2 += __shfl_xor_sync(0xffffffffu, a2, 16);
    a3 += __shfl_xor_sync(0xffffffffu, a3, 16);
    a4 += __shfl_xor_sync(0xffffffffu, a4, 16);
    a5 += __shfl_xor_sync(0xffffffffu, a5, 16);
    a6 += __shfl_xor_sync(0xffffffffu, a6, 16);
    a7 += __shfl_xor_sync(0xffffffffu, a7, 16);

    // transpose to strided dims via smem (conflict-free sW reads)
    if (hlf == 0) {
        float* st = &sStage[wblk][seg * 8];
        st[0] = a0; st[1] = a1; st[2] = a2; st[3] = a3;
        st[4] = a4; st[5] = a5; st[6] = a6; st[7] = a7;
    }
    __syncwarp();

    float na[4];
    #pragma unroll
    for (int t = 0; t < 4; t++) {
        float v = sStage[wblk][lane + 32 * t];
        na[t] = fmaxf(v * di + sBc[lane + 32 * t], 0.f);
    }

    float p[COUT];
    #pragma unroll
    for (int c = 0; c < COUT; c++) {
        p[c] = na[0] * sW[lane][c] + na[1] * sW[lane + 32][c]
             + na[2] * sW[lane + 64][c] + na[3] * sW[lane + 96][c];
    }

    // stage partials, 16-lane column reduce, lane-parallel softmax
    {
        float* pp = &sP[wblk][lane][0];
        #pragma unroll
        for (int c = 0; c < COUT; c++) pp[c] = p[c];
    }
    __syncwarp();
    if (lane < COUT) {
        float tot = 0.f;
        #pragma unroll
        for (int l = 0; l < 32; l++) tot += sP[wblk][l][lane];
        tot += sBl[lane];
        float mx = tot;
        #pragma unroll
        for (int off = 8; off > 0; off >>= 1)
            mx = fmaxf(mx, __shfl_xor_sync(0x0000ffffu, mx, off));
        float ex = expf(tot - mx);
        float sm = ex;
        #pragma unroll
        for (int off = 8; off > 0; off >>= 1)
            sm += __shfl_xor_sync(0x0000ffffu, sm, off);
        float lse = mx + logf(sm);
        out[(size_t)dst * COUT + lane] = tot - lse;
    }
}

// ---------------------------------------------------------------------------
extern "C" void kernel_launch(void* const* d_in, const int* in_sizes, int n_in,
                              void* d_out, int out_size) {
    const float* x      = (const float*)d_in[0];
    const void*  eidx   = d_in[1];
    const float* W_conv = (const float*)d_in[2];
    const float* b_conv = (const float*)d_in[3];
    const float* W_lin  = (const float*)d_in[4];
    const float* b_lin  = (const float*)d_in[5];
    float* out = (float*)d_out;

    static cudaStream_t s_side = nullptr;
    static cudaEvent_t  ev_fork = nullptr, ev_join = nullptr;
    static void* p_deg = nullptr;
    if (s_side == nullptr) {
        cudaStreamCreateWithFlags(&s_side, cudaStreamNonBlocking);
        cudaEventCreateWithFlags(&ev_fork, cudaEventDisableTiming);
        cudaEventCreateWithFlags(&ev_join, cudaEventDisableTiming);
        cudaGetSymbolAddress(&p_deg, g_deg);
        cudaFuncSetAttribute(k_gemm_tc,
                             cudaFuncAttributeMaxDynamicSharedMemorySize,
                             SMEM_DYN);
    }

    cudaEventRecord(ev_fork, 0);
    cudaStreamWaitEvent(s_side, ev_fork, 0);

    // SIDE: zero degrees -> sniff -> deg -> scan -> sort
    cudaMemsetAsync(p_deg, 0, NN * sizeof(int), s_side);
    k_sniff<<<1, 32, 0, s_side>>>((const int*)eidx);
    k_deg<<<1024, 256, 0, s_side>>>(eidx);
    k_scanA<<<NBLK, 1024, 0, s_side>>>();
    k_scanC<<<(NN + 255) / 256, 256, 0, s_side>>>();
    k_sort<<<1024, 256, 0, s_side>>>(eidx);
    cudaEventRecord(ev_join, s_side);

    // MAIN: W split then GEMM (independent of side chain)
    k_init_w<<<(CIN * HID + 255) / 256, 256>>>(W_conv);
    k_gemm_tc<<<(NN + 127) / 128, 256, SMEM_DYN>>>(x);

    // join, then aggregate + final
    cudaStreamWaitEvent(0, ev_join, 0);
    k_agg_final<<<(NN * 32 + 255) / 256, 256>>>(b_conv, W_lin, b_lin, out);
}

// round 12
// speedup vs baseline: 1.0992x; 1.0466x over previous
#include <cuda_runtime.h>
#include <cuda_bf16.h>
#include <cuda_fp16.h>
#include <math.h>
#include <stdint.h>

#define NN   100000
#define NE   1600000
#define CIN  256
#define HID  128
#define COUT 16
#define NBLK 98          // ceil(NN/1024)

// ---------------- scratch (__device__ globals; no allocs allowed) ----------
__device__ __half          g_hs16[(size_t)(NN + 1) * HID]; // raw h, +1 zero row
__device__ int             g_deg[NN];
__device__ float           g_dinv[NN];
__device__ int             g_psc[NN];
__device__ int             g_off[NN + 1];
__device__ int             g_wptr[NN];
__device__ int             g_bsum[NBLK];
__device__ int             g_esrc[NE];
__device__ int             g_is64;
__device__ int             g_work;
__device__ __nv_bfloat16   g_WT[HID * CIN];   // W^T bf16 [n][k]

__device__ __forceinline__ uint32_t smem_u32(const void* p) {
    uint32_t a;
    asm("{ .reg .u64 t; cvta.to.shared.u64 t, %1; cvt.u32.u64 %0, t; }"
        : "=r"(a) : "l"(p));
    return a;
}
__device__ __forceinline__ uint32_t swz128(uint32_t off) {
    return off ^ ((off >> 3) & 0x70);
}
__device__ __forceinline__ void ldsm_x4(uint32_t* r, uint32_t addr) {
    asm volatile("ldmatrix.sync.aligned.m8n8.x4.shared.b16 {%0,%1,%2,%3}, [%4];"
                 : "=r"(r[0]), "=r"(r[1]), "=r"(r[2]), "=r"(r[3]) : "r"(addr));
}
__device__ __forceinline__ void mma_bf16(float* d, const uint32_t* a,
                                         uint32_t b0, uint32_t b1) {
    asm volatile("mma.sync.aligned.m16n8k16.row.col.f32.bf16.bf16.f32 "
                 "{%0,%1,%2,%3}, {%4,%5,%6,%7}, {%8,%9}, {%0,%1,%2,%3};"
                 : "+f"(d[0]), "+f"(d[1]), "+f"(d[2]), "+f"(d[3])
                 : "r"(a[0]), "r"(a[1]), "r"(a[2]), "r"(a[3]), "r"(b0), "r"(b1));
}
__device__ __forceinline__ uint32_t cvt_bf16x2(float hi, float lo) {
    uint32_t r;
    asm("cvt.rn.bf16x2.f32 %0, %1, %2;" : "=r"(r) : "f"(hi), "f"(lo));
    return r;
}

// ---------------------------------------------------------------------------
// MAIN chain: W -> bf16 W^T, zero hs16 row NN, reset work queue
// ---------------------------------------------------------------------------
__global__ void k_init_w(const float* __restrict__ W) {
    int i = blockIdx.x * blockDim.x + threadIdx.x;
    if (i < CIN * HID) {
        int k = i >> 7, n = i & 127;
        g_WT[n * CIN + k] = __float2bfloat16_rn(W[i]);
    }
    if (i < 16)
        ((uint4*)(g_hs16 + (size_t)NN * HID))[i] = make_uint4(0u, 0u, 0u, 0u);
    if (i == 0) g_work = 0;
}

// SIDE chain: dtype sniff (1 warp)
__global__ void k_sniff(const int* __restrict__ e32) {
    if (threadIdx.x == 0) {
        int is64 = 1;
        #pragma unroll 1
        for (int j = 0; j < 64; j++)
            if (e32[2 * j + 1] != 0) { is64 = 0; break; }
        g_is64 = is64;
    }
}

__global__ void k_deg(const void* __restrict__ eptr) {
    const long long* e64 = (const long long*)eptr;
    const int*       e32 = (const int*)eptr;
    const int is64 = g_is64;
    for (int e = blockIdx.x * blockDim.x + threadIdx.x; e < NE;
         e += gridDim.x * blockDim.x) {
        int d = is64 ? (int)e64[NE + e] : e32[NE + e];
        atomicAdd(&g_deg[d], 1);
    }
}

__global__ __launch_bounds__(1024) void k_scanA() {
    __shared__ int ss[1024];
    const int t = threadIdx.x;
    const int i = blockIdx.x * 1024 + t;
    int v = (i < NN) ? g_deg[i] : 0;
    ss[t] = v;
    __syncthreads();
    #pragma unroll
    for (int off = 1; off < 1024; off <<= 1) {
        int add = (t >= off) ? ss[t - off] : 0;
        __syncthreads();
        ss[t] += add;
        __syncthreads();
    }
    if (i < NN) g_psc[i] = ss[t] - v;
    if (t == 1023) g_bsum[blockIdx.x] = ss[1023];
}

// scanC with inlined block-offset recompute
__global__ __launch_bounds__(256) void k_scanC() {
    __shared__ int s_boff;
    const int i = blockIdx.x * 256 + threadIdx.x;
    if (threadIdx.x == 0) {
        int blk = (blockIdx.x * 256) >> 10;
        int r0 = 0, r1 = 0, r2 = 0, r3 = 0;
        int b = 0;
        for (; b + 4 <= blk; b += 4) {
            r0 += g_bsum[b];     r1 += g_bsum[b + 1];
            r2 += g_bsum[b + 2]; r3 += g_bsum[b + 3];
        }
        for (; b < blk; b++) r0 += g_bsum[b];
        s_boff = r0 + r1 + r2 + r3;
    }
    __syncthreads();
    if (i < NN) {
        int o = g_psc[i] + s_boff;
        g_off[i]  = o;
        g_wptr[i] = o;
        g_dinv[i] = rsqrtf((float)(g_deg[i] + 1));
    }
    if (i == 0) g_off[NN] = NE;
}

__global__ void k_sort(const void* __restrict__ eptr) {
    const long long* e64 = (const long long*)eptr;
    const int*       e32 = (const int*)eptr;
    const int is64 = g_is64;
    for (int e = blockIdx.x * blockDim.x + threadIdx.x; e < NE;
         e += gridDim.x * blockDim.x) {
        int s = is64 ? (int)e64[e]      : e32[e];
        int d = is64 ? (int)e64[NE + e] : e32[NE + e];
        int pos = atomicAdd(&g_wptr[d], 1);
        g_esrc[pos] = s;
    }
}

// ---------------------------------------------------------------------------
// GEMM: h = x @ W_conv, single-pass bf16 mma.sync, fp32 accum.
// ---------------------------------------------------------------------------
#define TILE_B   16384
#define OFF_A    0
#define OFF_B    16384
#define SMEM_DYN (2 * TILE_B + 256)

__global__ __launch_bounds__(256, 2) void k_gemm_tc(const float* __restrict__ x) {
    extern __shared__ char dsm_raw[];
    char* const base = (char*)(((uintptr_t)dsm_raw + 127) & ~(uintptr_t)127);
    const uint32_t base_u = smem_u32(base);

    const int tid  = threadIdx.x;
    const int lane = tid & 31;
    const int wid  = tid >> 5;
    const int wm   = wid & 3;
    const int wn   = wid >> 2;
    const int row0 = blockIdx.x * 128;

    float acc[2][8][4];
    #pragma unroll
    for (int i = 0; i < 2; i++)
        #pragma unroll
        for (int j = 0; j < 8; j++)
            #pragma unroll
            for (int q = 0; q < 4; q++) acc[i][j][q] = 0.f;

    const float4* x4 = (const float4*)x;

    float4 v[8];
    #pragma unroll
    for (int i = 0; i < 8; i++) {
        int idx = i * 256 + tid;
        int r = idx >> 4, q = idx & 15;
        int node = row0 + r;
        v[i] = (node < NN) ? x4[(size_t)node * (CIN / 4) + q]
                           : make_float4(0.f, 0.f, 0.f, 0.f);
    }

    for (int c = 0; c < 4; c++) {
        #pragma unroll
        for (int i = 0; i < 8; i++) {
            int idx = i * 256 + tid;
            int r = idx >> 4, q = idx & 15;
            float4 w = v[i];
            uint32_t h01 = cvt_bf16x2(w.y, w.x);
            uint32_t h23 = cvt_bf16x2(w.w, w.z);
            uint32_t so = swz128((uint32_t)(r * 128 + q * 8));
            *(uint2*)(base + OFF_A + so) = make_uint2(h01, h23);
        }
        #pragma unroll
        for (int i = 0; i < 4; i++) {
            int idx = i * 256 + tid;
            int n = idx >> 3, u = idx & 7;
            uint32_t so = swz128((uint32_t)(n * 128 + u * 16));
            const char* src = (const char*)g_WT + n * (CIN * 2) + c * 128 + u * 16;
            *(uint4*)(base + OFF_B + so) = *(const uint4*)src;
        }
        __syncthreads();

        if (c < 3) {
            #pragma unroll
            for (int i = 0; i < 8; i++) {
                int idx = i * 256 + tid;
                int r = idx >> 4, q = idx & 15;
                int node = row0 + r;
                v[i] = (node < NN)
                     ? x4[(size_t)node * (CIN / 4) + (c + 1) * 16 + q]
                     : make_float4(0.f, 0.f, 0.f, 0.f);
            }
        }

        #pragma unroll
        for (int ks = 0; ks < 4; ks++) {
            uint32_t ah[2][4];
            #pragma unroll
            for (int mi = 0; mi < 2; mi++) {
                uint32_t r = (uint32_t)(wm * 32 + mi * 16 + (lane & 15));
                uint32_t kb = (uint32_t)(ks * 32 + (lane >> 4) * 16);
                ldsm_x4(ah[mi], base_u + OFF_A + swz128(r * 128 + kb));
            }
            #pragma unroll
            for (int nj2 = 0; nj2 < 4; nj2++) {
                uint32_t n = (uint32_t)(wn * 64 + nj2 * 16 + (lane & 7)
                                        + ((lane >> 4) << 3));
                uint32_t kb = (uint32_t)(ks * 32 + ((lane >> 3) & 1) * 16);
                uint32_t bh[4];
                ldsm_x4(bh, base_u + OFF_B + swz128(n * 128 + kb));
                #pragma unroll
                for (int mi = 0; mi < 2; mi++) {
                    mma_bf16(acc[mi][nj2 * 2 + 0], ah[mi], bh[0], bh[1]);
                    mma_bf16(acc[mi][nj2 * 2 + 1], ah[mi], bh[2], bh[3]);
                }
            }
        }
        __syncthreads();
    }

    const int group = lane >> 2;
    const int qp    = lane & 3;
    #pragma unroll
    for (int mi = 0; mi < 2; mi++) {
        #pragma unroll
        for (int half = 0; half < 2; half++) {
            int r = wm * 32 + mi * 16 + half * 8 + group;
            int node = row0 + r;
            if (node < NN) {
                __half* hrow = g_hs16 + (size_t)node * HID;
                #pragma unroll
                for (int nj = 0; nj < 8; nj++) {
                    int col = wn * 64 + nj * 8 + qp * 2;
                    __half2 hh = __floats2half2_rn(
                        acc[mi][nj][half * 2 + 0],
                        acc[mi][nj][half * 2 + 1]);
                    *(__half2*)(hrow + col) = hh;
                }
            }
        }
    }
}

// ---------------------------------------------------------------------------
// Aggregate + final linear + log_softmax.  PERSISTENT warps: each warp pulls
// chunks of 4 dst nodes from a global queue -> no intra-CTA straggler loss.
// ---------------------------------------------------------------------------
#define AGG_BLOCKS 592
#define CHUNK 4

__global__ __launch_bounds__(256) void k_agg_final(const float* __restrict__ bc,
                                                   const float* __restrict__ Wl,
                                                   const float* __restrict__ bl,
                                                   float* __restrict__ out) {
    __shared__ float sW[HID][COUT + 1];
    __shared__ float sBc[HID];
    __shared__ float sBl[COUT];
    __shared__ float sStage[8][HID];
    __shared__ float sP[8][32][COUT + 1];
    for (int i = threadIdx.x; i < HID * COUT; i += 256) {
        int d = i >> 4, c = i & 15;
        sW[d][c] = Wl[i];
    }
    for (int i = threadIdx.x; i < HID; i += 256) sBc[i] = bc[i];
    if (threadIdx.x < COUT) sBl[threadIdx.x] = bl[threadIdx.x];
    __syncthreads();

    const int lane = threadIdx.x & 31;
    const int wblk = threadIdx.x >> 5;
    const uint4* hp = (const uint4*)g_hs16;
    const int seg = lane & 15;
    const int hlf = lane >> 4;
    const __half2 hz = __floats2half2_rn(0.f, 0.f);

    for (;;) {
        int base_node;
        if (lane == 0) base_node = atomicAdd(&g_work, CHUNK);
        base_node = __shfl_sync(0xffffffffu, base_node, 0);
        if (base_node >= NN) break;
        int end_node = base_node + CHUNK;
        if (end_node > NN) end_node = NN;

        for (int dst = base_node; dst < end_node; dst++) {
            const int s0 = g_off[dst];
            const int s1 = g_off[dst + 1];
            const float di = g_dinv[dst];

            float a0, a1, a2, a3, a4, a5, a6, a7;
            {   // self row: half 0 dst row with coeff di, half 1 zero row
                int ssrc = hlf ? NN : dst;
                float cf = hlf ? 0.f : di;
                uint4 u = __ldg(hp + (size_t)ssrc * 16 + seg);
                float2 f0 = __half22float2(*(__half2*)&u.x);
                float2 f1 = __half22float2(*(__half2*)&u.y);
                float2 f2 = __half22float2(*(__half2*)&u.z);
                float2 f3 = __half22float2(*(__half2*)&u.w);
                a0 = f0.x * cf; a1 = f0.y * cf; a2 = f1.x * cf; a3 = f1.y * cf;
                a4 = f2.x * cf; a5 = f2.y * cf; a6 = f3.x * cf; a7 = f3.y * cf;
            }

            for (int b = s0; b < s1; b += 32) {
                int m = s1 - b; if (m > 32) m = 32;
                int   s   = (lane < m) ? __ldg(g_esrc + b + lane) : NN;
                float dsf = (lane < m) ? __ldg(g_dinv + s) : 0.f;
                __half2 dh2 = __float2half2_rn(dsf);
                uint32_t dcode = *(uint32_t*)&dh2;

                __half2 hc0 = hz, hc1 = hz, hc2 = hz, hc3 = hz;
                #pragma unroll 1
                for (int j = 0; j < m; j += 8) {
                    int      e0 = __shfl_sync(0xffffffffu, s,     j + 0 + hlf);
                    int      e1 = __shfl_sync(0xffffffffu, s,     j + 2 + hlf);
                    int      e2 = __shfl_sync(0xffffffffu, s,     j + 4 + hlf);
                    int      e3 = __shfl_sync(0xffffffffu, s,     j + 6 + hlf);
                    uint32_t q0 = __shfl_sync(0xffffffffu, dcode, j + 0 + hlf);
                    uint32_t q1 = __shfl_sync(0xffffffffu, dcode, j + 2 + hlf);
                    uint32_t q2 = __shfl_sync(0xffffffffu, dcode, j + 4 + hlf);
                    uint32_t q3 = __shfl_sync(0xffffffffu, dcode, j + 6 + hlf);
                    uint4 u0 = __ldg(hp + (size_t)e0 * 16 + seg);
                    uint4 u1 = __ldg(hp + (size_t)e1 * 16 + seg);
                    uint4 u2 = __ldg(hp + (size_t)e2 * 16 + seg);
                    uint4 u3 = __ldg(hp + (size_t)e3 * 16 + seg);
                    __half2 c0 = *(__half2*)&q0, c1 = *(__half2*)&q1;
                    __half2 c2 = *(__half2*)&q2, c3 = *(__half2*)&q3;
                    hc0 = __hfma2(*(__half2*)&u0.x, c0, hc0);
                    hc1 = __hfma2(*(__half2*)&u0.y, c0, hc1);
                    hc2 = __hfma2(*(__half2*)&u0.z, c0, hc2);
                    hc3 = __hfma2(*(__half2*)&u0.w, c0, hc3);
                    hc0 = __hfma2(*(__half2*)&u1.x, c1, hc0);
                    hc1 = __hfma2(*(__half2*)&u1.y, c1, hc1);
                    hc2 = __hfma2(*(__half2*)&u1.z, c1, hc2);
                    hc3 = __hfma2(*(__half2*)&u1.w, c1, hc3);
                    hc0 = __hfma2(*(__half2*)&u2.x, c2, hc0);
                    hc1 = __hfma2(*(__half2*)&u2.y, c2, hc1);
                    hc2 = __hfma2(*(__half2*)&u2.z, c2, hc2);
                    hc3 = __hfma2(*(__half2*)&u2.w, c2, hc3);
                    hc0 = __hfma2(*(__half2*)&u3.x, c3, hc0);
                    hc1 = __hfma2(*(__half2*)&u3.y, c3, hc1);
                    hc2 = __hfma2(*(__half2*)&u3.z, c3, hc2);
                    hc3 = __hfma2(*(__half2*)&u3.w, c3, hc3);
                    if (j == 8) {   // bound half-accum error
                        float2 f0 = __half22float2(hc0);
                        float2 f1 = __half22float2(hc1);
                        float2 f2 = __half22float2(hc2);
                        float2 f3 = __half22float2(hc3);
                        a0 += f0.x; a1 += f0.y; a2 += f1.x; a3 += f1.y;
                        a4 += f2.x; a5 += f2.y; a6 += f3.x; a7 += f3.y;
                        hc0 = hz; hc1 = hz; hc2 = hz; hc3 = hz;
                    }
                }
                {
                    float2 f0 = __half22float2(hc0);
                    float2 f1 = __half22float2(hc1);
                    float2 f2 = __half22float2(hc2);
                    float2 f3 = __half22float2(hc3);
                    a0 += f0.x; a1 += f0.y; a2 += f1.x; a3 += f1.y;
                    a4 += f2.x; a5 += f2.y; a6 += f3.x; a7 += f3.y;
                }
            }

            a0 += __shfl_xor_sync(0xffffffffu, a0, 16);
            a1 += __shfl_xor_sync(0xffffffffu, a1, 16);
            a2 += __shfl_xor_sync(0xffffffffu, a2, 16);
            a3 += __shfl_xor_sync(0xffffffffu, a3, 16);
            a4 += __shfl_xor_sync(0xffffffffu, a4, 16);
            a5 += __shfl_xor_sync(0xffffffffu, a5, 16);
            a6 += __shfl_xor_sync(0xffffffffu, a6, 16);
            a7 += __shfl_xor_sync(0xffffffffu, a7, 16);

            if (hlf == 0) {
                float* st = &sStage[wblk][seg * 8];
                st[0] = a0; st[1] = a1; st[2] = a2; st[3] = a3;
                st[4] = a4; st[5] = a5; st[6] = a6; st[7] = a7;
            }
            __syncwarp();

            float na[4];
            #pragma unroll
            for (int t = 0; t < 4; t++) {
                float v = sStage[wblk][lane + 32 * t];
                na[t] = fmaxf(v * di + sBc[lane + 32 * t], 0.f);
            }

            float p[COUT];
            #pragma unroll
            for (int c = 0; c < COUT; c++) {
                p[c] = na[0] * sW[lane][c] + na[1] * sW[lane + 32][c]
                     + na[2] * sW[lane + 64][c] + na[3] * sW[lane + 96][c];
            }

            {
                float* pp = &sP[wblk][lane][0];
                #pragma unroll
                for (int c = 0; c < COUT; c++) pp[c] = p[c];
            }
            __syncwarp();
            if (lane < COUT) {
                float tot = 0.f;
                #pragma unroll
                for (int l = 0; l < 32; l++) tot += sP[wblk][l][lane];
                tot += sBl[lane];
                float mx = tot;
                #pragma unroll
                for (int off = 8; off > 0; off >>= 1)
                    mx = fmaxf(mx, __shfl_xor_sync(0x0000ffffu, mx, off));
                float ex = expf(tot - mx);
                float sm = ex;
                #pragma unroll
                for (int off = 8; off > 0; off >>= 1)
                    sm += __shfl_xor_sync(0x0000ffffu, sm, off);
                float lse = mx + logf(sm);
                out[(size_t)dst * COUT + lane] = tot - lse;
            }
            __syncwarp();
        }
    }
}

// ---------------------------------------------------------------------------
extern "C" void kernel_launch(void* const* d_in, const int* in_sizes, int n_in,
                              void* d_out, int out_size) {
    const float* x      = (const float*)d_in[0];
    const void*  eidx   = d_in[1];
    const float* W_conv = (const float*)d_in[2];
    const float* b_conv = (const float*)d_in[3];
    const float* W_lin  = (const float*)d_in[4];
    const float* b_lin  = (const float*)d_in[5];
    float* out = (float*)d_out;

    static cudaStream_t s_side = nullptr;
    static cudaEvent_t  ev_fork = nullptr, ev_join = nullptr;
    static void* p_deg = nullptr;
    if (s_side == nullptr) {
        cudaStreamCreateWithFlags(&s_side, cudaStreamNonBlocking);
        cudaEventCreateWithFlags(&ev_fork, cudaEventDisableTiming);
        cudaEventCreateWithFlags(&ev_join, cudaEventDisableTiming);
        cudaGetSymbolAddress(&p_deg, g_deg);
        cudaFuncSetAttribute(k_gemm_tc,
                             cudaFuncAttributeMaxDynamicSharedMemorySize,
                             SMEM_DYN);
    }

    cudaEventRecord(ev_fork, 0);
    cudaStreamWaitEvent(s_side, ev_fork, 0);

    // SIDE: zero degrees -> sniff -> deg -> scan -> sort
    cudaMemsetAsync(p_deg, 0, NN * sizeof(int), s_side);
    k_sniff<<<1, 32, 0, s_side>>>((const int*)eidx);
    k_deg<<<1024, 256, 0, s_side>>>(eidx);
    k_scanA<<<NBLK, 1024, 0, s_side>>>();
    k_scanC<<<(NN + 255) / 256, 256, 0, s_side>>>();
    k_sort<<<1024, 256, 0, s_side>>>(eidx);
    cudaEventRecord(ev_join, s_side);

    // MAIN: W split (+ work-queue reset) then GEMM
    k_init_w<<<(CIN * HID + 255) / 256, 256>>>(W_conv);
    k_gemm_tc<<<(NN + 127) / 128, 256, SMEM_DYN>>>(x);

    // join, then persistent aggregate + final
    cudaStreamWaitEvent(0, ev_join, 0);
    k_agg_final<<<AGG_BLOCKS, 256>>>(b_conv, W_lin, b_lin, out);
}